// round 1
// baseline (speedup 1.0000x reference)
#include <cuda_runtime.h>
#include <math.h>

#define Dm   1024
#define Vm   32000
#define Hm   16
#define DHm  64
#define Bm   32
#define Sm   100
#define Mm   3200          // B*S
#define FFm  4096
#define Lm   2
#define LN_EPS 1e-5f
#define Q_EPS  1e-6f

// ---------------- scratch (static device globals; no allocation) -------------
__device__ float g_h  [Mm * Dm];
__device__ float g_tmp[Mm * Dm];
__device__ float g_qkv[Mm * 3 * Dm];
__device__ float g_ctx[Mm * Dm];
__device__ float g_ff [Mm * FFm];
__device__ float g_tw [(size_t)Vm * Dm];
__device__ float g_partial[1024];
__device__ float g_gval;

// ---------------- helpers ----------------------------------------------------
__device__ __forceinline__ float gelu_exact(float x) {
    return 0.5f * x * (1.0f + erff(x * 0.70710678118654752440f));
}

__device__ __forceinline__ float block_reduce_sum(float v) {
    __shared__ float red[32];
    int lane = threadIdx.x & 31;
    int wid  = threadIdx.x >> 5;
#pragma unroll
    for (int o = 16; o > 0; o >>= 1) v += __shfl_xor_sync(0xffffffffu, v, o);
    if (lane == 0) red[wid] = v;
    __syncthreads();
    int nw = blockDim.x >> 5;
    float s = (threadIdx.x < nw) ? red[threadIdx.x] : 0.f;
    if (wid == 0) {
#pragma unroll
        for (int o = 16; o > 0; o >>= 1) s += __shfl_xor_sync(0xffffffffu, s, o);
        if (lane == 0) red[0] = s;
    }
    __syncthreads();
    float r = red[0];
    __syncthreads();     // protect red[] before any subsequent call
    return r;
}

// ---------------- embedding gather -------------------------------------------
__global__ void embed_kernel(const int* __restrict__ x,
                             const float* __restrict__ embed,
                             const float* __restrict__ pos) {
    int i = blockIdx.x * blockDim.x + threadIdx.x;
    if (i >= Mm * Dm) return;
    int m = i / Dm, d = i - m * Dm;
    int s = m % Sm;
    g_h[i] = embed[(size_t)x[m] * Dm + d] + pos[s * Dm + d];
}

// ---------------- SGEMM: C[M,N] = A[M,K] * B[N,K]^T + bias (opt GELU) --------
// 128x128 block, BK=16, 256 threads, 8x8 per thread.
template<bool GELU, bool SWAP>
__global__ __launch_bounds__(256, 2) void sgemm_kernel(
    const float* __restrict__ A, const float* __restrict__ Bmat,
    const float* __restrict__ bias, float* __restrict__ C,
    int M, int N, int K)
{
    __shared__ float As[16][128];
    __shared__ float Bs[16][128];
    const int tid = threadIdx.x;
    const int mt = SWAP ? blockIdx.x : blockIdx.y;
    const int nt = SWAP ? blockIdx.y : blockIdx.x;
    const float* Ab = A    + (size_t)mt * 128 * K;
    const float* Bb = Bmat + (size_t)nt * 128 * K;
    const int lr = tid >> 2;           // 0..63
    const int lc = (tid & 3) << 2;     // 0,4,8,12
    const int ty = tid >> 4;           // 0..15
    const int tx = tid & 15;           // 0..15

    float acc[8][8];
#pragma unroll
    for (int i = 0; i < 8; i++)
#pragma unroll
        for (int j = 0; j < 8; j++) acc[i][j] = 0.f;

    for (int k0 = 0; k0 < K; k0 += 16) {
        float4 a0 = *(const float4*)(Ab + (size_t)lr        * K + k0 + lc);
        float4 a1 = *(const float4*)(Ab + (size_t)(lr + 64) * K + k0 + lc);
        float4 b0 = *(const float4*)(Bb + (size_t)lr        * K + k0 + lc);
        float4 b1 = *(const float4*)(Bb + (size_t)(lr + 64) * K + k0 + lc);
        __syncthreads();   // previous tile fully consumed
        As[lc + 0][lr] = a0.x; As[lc + 1][lr] = a0.y; As[lc + 2][lr] = a0.z; As[lc + 3][lr] = a0.w;
        As[lc + 0][lr + 64] = a1.x; As[lc + 1][lr + 64] = a1.y; As[lc + 2][lr + 64] = a1.z; As[lc + 3][lr + 64] = a1.w;
        Bs[lc + 0][lr] = b0.x; Bs[lc + 1][lr] = b0.y; Bs[lc + 2][lr] = b0.z; Bs[lc + 3][lr] = b0.w;
        Bs[lc + 0][lr + 64] = b1.x; Bs[lc + 1][lr + 64] = b1.y; Bs[lc + 2][lr + 64] = b1.z; Bs[lc + 3][lr + 64] = b1.w;
        __syncthreads();
#pragma unroll
        for (int kk = 0; kk < 16; kk++) {
            float4 av0 = *(const float4*)&As[kk][ty * 8];
            float4 av1 = *(const float4*)&As[kk][ty * 8 + 4];
            float4 bv0 = *(const float4*)&Bs[kk][tx * 8];
            float4 bv1 = *(const float4*)&Bs[kk][tx * 8 + 4];
            float a[8] = {av0.x, av0.y, av0.z, av0.w, av1.x, av1.y, av1.z, av1.w};
            float b[8] = {bv0.x, bv0.y, bv0.z, bv0.w, bv1.x, bv1.y, bv1.z, bv1.w};
#pragma unroll
            for (int i = 0; i < 8; i++)
#pragma unroll
                for (int j = 0; j < 8; j++) acc[i][j] += a[i] * b[j];
        }
    }

    const int cm = mt * 128 + ty * 8;
    const int cn = nt * 128 + tx * 8;
    float bv[8];
#pragma unroll
    for (int j = 0; j < 8; j++) bv[j] = bias[cn + j];
#pragma unroll
    for (int i = 0; i < 8; i++) {
        float o[8];
#pragma unroll
        for (int j = 0; j < 8; j++) {
            float v = acc[i][j] + bv[j];
            o[j] = GELU ? gelu_exact(v) : v;
        }
        float* crow = C + (size_t)(cm + i) * N + cn;
        *(float4*)(crow)     = make_float4(o[0], o[1], o[2], o[3]);
        *(float4*)(crow + 4) = make_float4(o[4], o[5], o[6], o[7]);
    }
}

// ---------------- fused attention: one block per (b,h) -----------------------
__global__ __launch_bounds__(128) void attn_kernel(const float* __restrict__ qkv,
                                                   float* __restrict__ ctx) {
    __shared__ float Ks[Sm][DHm];
    __shared__ float Vs[Sm][DHm];
    const int h = blockIdx.x % Hm;
    const int b = blockIdx.x / Hm;
    const int base = b * Sm;
    const int tid = threadIdx.x;

    for (int idx = tid; idx < Sm * DHm; idx += blockDim.x) {
        int r = idx / DHm, c = idx - r * DHm;
        size_t row = (size_t)(base + r) * (3 * Dm);
        Ks[r][c] = qkv[row + Dm     + h * DHm + c];
        Vs[r][c] = qkv[row + 2 * Dm + h * DHm + c];
    }
    __syncthreads();

    if (tid < Sm) {
        float q[DHm];
        const float* qp = qkv + (size_t)(base + tid) * (3 * Dm) + h * DHm;
#pragma unroll
        for (int d = 0; d < DHm; d++) q[d] = qp[d];

        float p[Sm];
        float mx = -1e30f;
        for (int k = 0; k < Sm; k++) {
            float s = 0.f;
#pragma unroll
            for (int d = 0; d < DHm; d++) s += q[d] * Ks[k][d];
            s *= 0.125f;                       // 1/sqrt(64)
            p[k] = s;
            mx = fmaxf(mx, s);
        }
        float sum = 0.f;
        for (int k = 0; k < Sm; k++) { p[k] = expf(p[k] - mx); sum += p[k]; }
        float inv = 1.f / sum;

        float* cp = ctx + (size_t)(base + tid) * Dm + h * DHm;
        for (int d = 0; d < DHm; d++) {
            float a = 0.f;
            for (int k = 0; k < Sm; k++) a += p[k] * Vs[k][d];
            cp[d] = a * inv;
        }
    }
}

// ---------------- residual + layernorm (in place on g_h) ---------------------
__global__ __launch_bounds__(256) void ln_kernel(float* __restrict__ h,
                                                 const float* __restrict__ delta,
                                                 const float* __restrict__ w,
                                                 const float* __restrict__ bias) {
    const int row = blockIdx.x;
    const size_t off = (size_t)row * Dm;
    float v[4];
    float s = 0.f;
#pragma unroll
    for (int i = 0; i < 4; i++) {
        int c = threadIdx.x + i * 256;
        v[i] = h[off + c] + delta[off + c];
        s += v[i];
    }
    float mean = block_reduce_sum(s) * (1.f / Dm);
    float s2 = 0.f;
#pragma unroll
    for (int i = 0; i < 4; i++) { float d = v[i] - mean; s2 += d * d; }
    float var = block_reduce_sum(s2) * (1.f / Dm);
    float inv = rsqrtf(var + LN_EPS);
#pragma unroll
    for (int i = 0; i < 4; i++) {
        int c = threadIdx.x + i * 256;
        h[off + c] = (v[i] - mean) * inv * w[c] + bias[c];
    }
}

// ---------------- decoder weight scale + quantize ----------------------------
__global__ __launch_bounds__(256) void absum_kernel(const float* __restrict__ w) {
    float s = 0.f;
    const size_t total = (size_t)Vm * Dm;
    for (size_t i = (size_t)blockIdx.x * blockDim.x + threadIdx.x; i < total;
         i += (size_t)gridDim.x * blockDim.x)
        s += fabsf(w[i]);
    float bs = block_reduce_sum(s);
    if (threadIdx.x == 0) g_partial[blockIdx.x] = bs;
}

__global__ __launch_bounds__(256) void finalize_g_kernel() {
    float s = 0.f;
    for (int i = threadIdx.x; i < 1024; i += 256) s += g_partial[i];
    float t = block_reduce_sum(s);
    if (threadIdx.x == 0) g_gval = t / (float)((size_t)Vm * Dm);
}

__global__ void quant_kernel(const float* __restrict__ w) {
    size_t i = (size_t)blockIdx.x * blockDim.x + threadIdx.x;
    if (i >= (size_t)Vm * Dm) return;
    float inv = 1.f / (g_gval + Q_EPS);
    float t = rintf(w[i] * inv);             // round-half-to-even == jnp.round
    g_tw[i] = fminf(1.f, fmaxf(-1.f, t));
}

// ---------------- host orchestration -----------------------------------------
extern "C" void kernel_launch(void* const* d_in, const int* in_sizes, int n_in,
                              void* d_out, int out_size) {
    const int*   x     = (const int*)  d_in[0];
    const float* embed = (const float*)d_in[1];
    const float* pos   = (const float*)d_in[2];
    const float* Wqkv  = (const float*)d_in[3];
    const float* bqkv  = (const float*)d_in[4];
    const float* Wo    = (const float*)d_in[5];
    const float* bo    = (const float*)d_in[6];
    const float* ln1w  = (const float*)d_in[7];
    const float* ln1b  = (const float*)d_in[8];
    const float* W1    = (const float*)d_in[9];
    const float* b1    = (const float*)d_in[10];
    const float* W2    = (const float*)d_in[11];
    const float* b2    = (const float*)d_in[12];
    const float* ln2w  = (const float*)d_in[13];
    const float* ln2b  = (const float*)d_in[14];
    const float* decw  = (const float*)d_in[15];
    const float* decb  = (const float*)d_in[16];
    float* out = (float*)d_out;

    float *h, *tmp, *qkv, *ctx, *ff, *tw;
    cudaGetSymbolAddress((void**)&h,   g_h);
    cudaGetSymbolAddress((void**)&tmp, g_tmp);
    cudaGetSymbolAddress((void**)&qkv, g_qkv);
    cudaGetSymbolAddress((void**)&ctx, g_ctx);
    cudaGetSymbolAddress((void**)&ff,  g_ff);
    cudaGetSymbolAddress((void**)&tw,  g_tw);

    // 1. embedding + positional
    embed_kernel<<<(Mm * Dm + 255) / 256, 256>>>(x, embed, pos);

    // 2. encoder layers
    for (int l = 0; l < Lm; l++) {
        const float* Wqkv_l = Wqkv + (size_t)l * 3 * Dm * Dm;
        const float* bqkv_l = bqkv + (size_t)l * 3 * Dm;
        const float* Wo_l   = Wo   + (size_t)l * Dm * Dm;
        const float* bo_l   = bo   + (size_t)l * Dm;
        const float* W1_l   = W1   + (size_t)l * FFm * Dm;
        const float* b1_l   = b1   + (size_t)l * FFm;
        const float* W2_l   = W2   + (size_t)l * Dm * FFm;
        const float* b2_l   = b2   + (size_t)l * Dm;

        // qkv = h @ Wqkv^T + bqkv      [3200, 3072]
        sgemm_kernel<false, false><<<dim3(3 * Dm / 128, Mm / 128), 256>>>(
            h, Wqkv_l, bqkv_l, qkv, Mm, 3 * Dm, Dm);

        // attention -> ctx             [3200, 1024]
        attn_kernel<<<Bm * Hm, 128>>>(qkv, ctx);

        // attn_out = ctx @ Wo^T + bo   [3200, 1024]
        sgemm_kernel<false, false><<<dim3(Dm / 128, Mm / 128), 256>>>(
            ctx, Wo_l, bo_l, tmp, Mm, Dm, Dm);

        // h = LN(h + attn_out)
        ln_kernel<<<Mm, 256>>>(h, tmp, ln1w + (size_t)l * Dm, ln1b + (size_t)l * Dm);

        // ff = gelu(h @ W1^T + b1)     [3200, 4096]
        sgemm_kernel<true, false><<<dim3(FFm / 128, Mm / 128), 256>>>(
            h, W1_l, b1_l, ff, Mm, FFm, Dm);

        // ff2 = ff @ W2^T + b2         [3200, 1024]
        sgemm_kernel<false, false><<<dim3(Dm / 128, Mm / 128), 256>>>(
            ff, W2_l, b2_l, tmp, Mm, Dm, FFm);

        // h = LN(h + ff2)
        ln_kernel<<<Mm, 256>>>(h, tmp, ln2w + (size_t)l * Dm, ln2b + (size_t)l * Dm);
    }

    // 3. ternary decoder
    absum_kernel<<<1024, 256>>>(decw);
    finalize_g_kernel<<<1, 256>>>();
    quant_kernel<<<(int)(((size_t)Vm * Dm + 255) / 256), 256>>>(decw);

    // out = h @ tw^T + dec_b           [3200, 32000]
    // SWAP grid: M-tiles in x so each tw panel is L2-resident across all M-tiles
    sgemm_kernel<false, true><<<dim3(Mm / 128, Vm / 128), 256>>>(
        h, tw, decb, out, Mm, Vm, Dm);
}

// round 4
// speedup vs baseline: 1.4467x; 1.4467x over previous
#include <cuda_runtime.h>
#include <cuda_fp16.h>
#include <math.h>
#include <stdint.h>

#define Dm   1024
#define Vm   32000
#define Hm   16
#define DHm  64
#define Bm   32
#define Sm   100
#define Mm   3200          // B*S
#define FFm  4096
#define Lm   2
#define LN_EPS 1e-5f
#define Q_EPS  1e-6f

// ---------------- scratch (static device globals; no allocation) -------------
__device__ float g_h  [Mm * Dm];
__device__ float g_tmp[Mm * Dm];
__device__ float g_qkv[Mm * 3 * Dm];
__device__ float g_ctx[Mm * Dm];
__device__ float g_ff [Mm * FFm];
__device__ __half g_ah[Mm * FFm];          // activation hi split (max 3200x4096)
__device__ __half g_al[Mm * FFm];          // activation lo split
__device__ __half g_wh[FFm * Dm];          // weight hi split (max 4096x1024)
__device__ __half g_wl[FFm * Dm];          // weight lo split
__device__ __half g_twq[(size_t)Vm * Dm];  // ternary decoder weights (exact fp16)
__device__ float g_partial[1024];
__device__ float g_gval;

// ---------------- small helpers ----------------------------------------------
__device__ __forceinline__ uint32_t smem_u32(const void* p) {
    uint32_t a;
    asm("{ .reg .u64 t; cvta.to.shared.u64 t, %1; cvt.u32.u64 %0, t; }" : "=r"(a) : "l"(p));
    return a;
}

__device__ __forceinline__ float gelu_exact(float x) {
    return 0.5f * x * (1.0f + erff(x * 0.70710678118654752440f));
}

__device__ __forceinline__ float block_reduce_sum(float v) {
    __shared__ float red[32];
    int lane = threadIdx.x & 31;
    int wid  = threadIdx.x >> 5;
#pragma unroll
    for (int o = 16; o > 0; o >>= 1) v += __shfl_xor_sync(0xffffffffu, v, o);
    if (lane == 0) red[wid] = v;
    __syncthreads();
    int nw = blockDim.x >> 5;
    float s = (threadIdx.x < nw) ? red[threadIdx.x] : 0.f;
    if (wid == 0) {
#pragma unroll
        for (int o = 16; o > 0; o >>= 1) s += __shfl_xor_sync(0xffffffffu, s, o);
        if (lane == 0) red[0] = s;
    }
    __syncthreads();
    float r = red[0];
    __syncthreads();
    return r;
}

// ---------------- elementwise kernels -----------------------------------------
__global__ void embed_kernel(const int* __restrict__ x,
                             const float* __restrict__ embed,
                             const float* __restrict__ pos) {
    int i = blockIdx.x * blockDim.x + threadIdx.x;
    if (i >= Mm * Dm) return;
    int m = i / Dm, d = i - m * Dm;
    int s = m % Sm;
    g_h[i] = embed[(size_t)x[m] * Dm + d] + pos[s * Dm + d];
}

// fp32 -> (hi, lo) fp16 split
__global__ void split_kernel(const float* __restrict__ src,
                             __half* __restrict__ hi,
                             __half* __restrict__ lo, int n) {
    int i = blockIdx.x * blockDim.x + threadIdx.x;
    if (i >= n) return;
    float x = src[i];
    __half h = __float2half_rn(x);
    hi[i] = h;
    lo[i] = __float2half_rn(x - __half2float(h));
}

// ---------------- mma.sync GEMM -----------------------------------------------
// C[M,N] = sum_seg A_s[M,K] * B_s[N,K]^T + bias (opt GELU)
// 128x128 CTA tile, BK=32, 256 threads (8 warps, 2x4), warp tile 64x32.
// Double-buffered cp.async; smem rows padded to 40 halves (80B) -> conflict-free
// ldmatrix (row stride 80B cycles all eight 16B bank groups).

#define SROW 40   // halves per smem row (32 data + 8 pad)

__device__ __forceinline__ void cp_async16(uint32_t dst, const void* src) {
    asm volatile("cp.async.cg.shared.global [%0], [%1], 16;" :: "r"(dst), "l"(src));
}
__device__ __forceinline__ void ldsm_x4(uint32_t* r, uint32_t addr) {
    asm volatile("ldmatrix.sync.aligned.m8n8.x4.shared.b16 {%0,%1,%2,%3}, [%4];"
                 : "=r"(r[0]), "=r"(r[1]), "=r"(r[2]), "=r"(r[3]) : "r"(addr));
}
__device__ __forceinline__ void mma_16816(float* d, const uint32_t* a, uint32_t b0, uint32_t b1) {
    asm volatile(
        "mma.sync.aligned.m16n8k16.row.col.f32.f16.f16.f32 "
        "{%0,%1,%2,%3}, {%4,%5,%6,%7}, {%8,%9}, {%0,%1,%2,%3};"
        : "+f"(d[0]), "+f"(d[1]), "+f"(d[2]), "+f"(d[3])
        : "r"(a[0]), "r"(a[1]), "r"(a[2]), "r"(a[3]), "r"(b0), "r"(b1));
}

template<bool GELU>
__global__ __launch_bounds__(256) void gemm_mma(
    const __half* __restrict__ A0, const __half* __restrict__ A1,
    const __half* __restrict__ A2,
    const __half* __restrict__ B0, const __half* __restrict__ B1,
    const __half* __restrict__ B2,
    int nseg, const float* __restrict__ bias, float* __restrict__ C,
    int N, int K)
{
    __shared__ __align__(16) __half sA[2][128 * SROW];
    __shared__ __align__(16) __half sB[2][128 * SROW];

    const int tid = threadIdx.x;
    const int wid = tid >> 5;
    const int lane = tid & 31;
    const int warp_m = wid & 1;        // 0..1
    const int warp_n = wid >> 1;       // 0..3
    const int mt = blockIdx.x;
    const int nt = blockIdx.y;

    const __half* As[3] = {A0, A1, A2};
    const __half* Bs[3] = {B0, B1, B2};
    const int tilesPerSeg = K >> 5;          // K/32
    const int T = nseg * tilesPerSeg;

    float acc[4][4][4];
#pragma unroll
    for (int i = 0; i < 4; i++)
#pragma unroll
        for (int j = 0; j < 4; j++)
#pragma unroll
            for (int r = 0; r < 4; r++) acc[i][j][r] = 0.f;

    // loader mapping: 2 iters x (idx = tid + 256*j): row = idx>>2, chunk = idx&3
    const int l_row0 = tid >> 2;
    const int l_ch   = (tid & 3) * 8;        // halves offset within row

    // ldmatrix lane addressing
    const int q = lane >> 3, lr = lane & 7;
    // A: row = warp_m*64 + mi*16 + (q&1)*8 + lr ; kcol = ks*16 + (q>>1)*8
    const int a_row_base = warp_m * 64 + (q & 1) * 8 + lr;
    const int a_kq = (q >> 1) * 8;
    // B: row = warp_n*32 + jp*16 + (q>>1)*8 + lr ; kcol = ks*16 + (q&1)*8
    const int b_row_base = warp_n * 32 + (q >> 1) * 8 + lr;
    const int b_kq = (q & 1) * 8;

#define PREFETCH(it, buf)                                                        \
    {                                                                            \
        int seg_ = (it) / tilesPerSeg;                                           \
        int k0_  = ((it) - seg_ * tilesPerSeg) << 5;                             \
        const __half* Ap_ = As[seg_] + (size_t)(mt * 128) * K + k0_;             \
        const __half* Bp_ = Bs[seg_] + (size_t)(nt * 128) * K + k0_;             \
        _Pragma("unroll")                                                        \
        for (int j_ = 0; j_ < 2; j_++) {                                         \
            int row_ = l_row0 + j_ * 64;                                         \
            uint32_t da = smem_u32(&sA[buf][row_ * SROW + l_ch]);                \
            uint32_t db = smem_u32(&sB[buf][row_ * SROW + l_ch]);                \
            cp_async16(da, Ap_ + (size_t)row_ * K + l_ch);                       \
            cp_async16(db, Bp_ + (size_t)row_ * K + l_ch);                       \
        }                                                                        \
    }

    PREFETCH(0, 0);
    asm volatile("cp.async.commit_group;" ::: "memory");

    for (int it = 0; it < T; it++) {
        const int buf = it & 1;
        if (it + 1 < T) {
            PREFETCH(it + 1, buf ^ 1);
            asm volatile("cp.async.commit_group;" ::: "memory");
            asm volatile("cp.async.wait_group 1;" ::: "memory");
        } else {
            asm volatile("cp.async.wait_group 0;" ::: "memory");
        }
        __syncthreads();

        const __half* sAb = sA[buf];
        const __half* sBb = sB[buf];
#pragma unroll
        for (int ks = 0; ks < 2; ks++) {
            uint32_t a[4][4];
#pragma unroll
            for (int mi = 0; mi < 4; mi++) {
                uint32_t addr = smem_u32(&sAb[(a_row_base + mi * 16) * SROW + ks * 16 + a_kq]);
                ldsm_x4(a[mi], addr);
            }
            uint32_t b[2][4];
#pragma unroll
            for (int jp = 0; jp < 2; jp++) {
                uint32_t addr = smem_u32(&sBb[(b_row_base + jp * 16) * SROW + ks * 16 + b_kq]);
                ldsm_x4(b[jp], addr);
            }
#pragma unroll
            for (int mi = 0; mi < 4; mi++)
#pragma unroll
                for (int nj = 0; nj < 4; nj++) {
                    int jp = nj >> 1, h = nj & 1;
                    mma_16816(acc[mi][nj], a[mi], b[jp][h * 2], b[jp][h * 2 + 1]);
                }
        }
        __syncthreads();
    }

    // epilogue
    const int g  = lane >> 2;
    const int tg = lane & 3;
#pragma unroll
    for (int mi = 0; mi < 4; mi++) {
#pragma unroll
        for (int nj = 0; nj < 4; nj++) {
            int row = mt * 128 + warp_m * 64 + mi * 16 + g;
            int col = nt * 128 + warp_n * 32 + nj * 8 + tg * 2;
            float b0 = bias[col], b1 = bias[col + 1];
            float v0 = acc[mi][nj][0] + b0;
            float v1 = acc[mi][nj][1] + b1;
            float v2 = acc[mi][nj][2] + b0;
            float v3 = acc[mi][nj][3] + b1;
            if (GELU) { v0 = gelu_exact(v0); v1 = gelu_exact(v1);
                        v2 = gelu_exact(v2); v3 = gelu_exact(v3); }
            *(float2*)(C + (size_t)row * N + col)       = make_float2(v0, v1);
            *(float2*)(C + (size_t)(row + 8) * N + col) = make_float2(v2, v3);
        }
    }
}

// ---------------- fused attention: one block per (b,h) -----------------------
__global__ __launch_bounds__(128) void attn_kernel(const float* __restrict__ qkv,
                                                   float* __restrict__ ctx) {
    __shared__ float Ks[Sm][DHm];
    __shared__ float Vs[Sm][DHm];
    const int h = blockIdx.x % Hm;
    const int b = blockIdx.x / Hm;
    const int base = b * Sm;
    const int tid = threadIdx.x;

    for (int idx = tid; idx < Sm * DHm; idx += blockDim.x) {
        int r = idx / DHm, c = idx - r * DHm;
        size_t row = (size_t)(base + r) * (3 * Dm);
        Ks[r][c] = qkv[row + Dm     + h * DHm + c];
        Vs[r][c] = qkv[row + 2 * Dm + h * DHm + c];
    }
    __syncthreads();

    if (tid < Sm) {
        float q[DHm];
        const float* qp = qkv + (size_t)(base + tid) * (3 * Dm) + h * DHm;
#pragma unroll
        for (int d = 0; d < DHm; d++) q[d] = qp[d];

        float p[Sm];
        float mx = -1e30f;
        for (int k = 0; k < Sm; k++) {
            float s = 0.f;
#pragma unroll
            for (int d = 0; d < DHm; d++) s += q[d] * Ks[k][d];
            s *= 0.125f;
            p[k] = s;
            mx = fmaxf(mx, s);
        }
        float sum = 0.f;
        for (int k = 0; k < Sm; k++) { p[k] = expf(p[k] - mx); sum += p[k]; }
        float inv = 1.f / sum;

        float* cp = ctx + (size_t)(base + tid) * Dm + h * DHm;
        for (int d = 0; d < DHm; d++) {
            float a = 0.f;
            for (int k = 0; k < Sm; k++) a += p[k] * Vs[k][d];
            cp[d] = a * inv;
        }
    }
}

// ---------------- residual + layernorm (in place on g_h) ---------------------
__global__ __launch_bounds__(256) void ln_kernel(float* __restrict__ h,
                                                 const float* __restrict__ delta,
                                                 const float* __restrict__ w,
                                                 const float* __restrict__ bias) {
    const int row = blockIdx.x;
    const size_t off = (size_t)row * Dm;
    float v[4];
    float s = 0.f;
#pragma unroll
    for (int i = 0; i < 4; i++) {
        int c = threadIdx.x + i * 256;
        v[i] = h[off + c] + delta[off + c];
        s += v[i];
    }
    float mean = block_reduce_sum(s) * (1.f / Dm);
    float s2 = 0.f;
#pragma unroll
    for (int i = 0; i < 4; i++) { float d = v[i] - mean; s2 += d * d; }
    float var = block_reduce_sum(s2) * (1.f / Dm);
    float inv = rsqrtf(var + LN_EPS);
#pragma unroll
    for (int i = 0; i < 4; i++) {
        int c = threadIdx.x + i * 256;
        h[off + c] = (v[i] - mean) * inv * w[c] + bias[c];
    }
}

// ---------------- decoder weight scale + quantize ----------------------------
__global__ __launch_bounds__(256) void absum_kernel(const float* __restrict__ w) {
    float s = 0.f;
    const size_t total = (size_t)Vm * Dm;
    for (size_t i = (size_t)blockIdx.x * blockDim.x + threadIdx.x; i < total;
         i += (size_t)gridDim.x * blockDim.x)
        s += fabsf(w[i]);
    float bs = block_reduce_sum(s);
    if (threadIdx.x == 0) g_partial[blockIdx.x] = bs;
}

__global__ __launch_bounds__(256) void finalize_g_kernel() {
    float s = 0.f;
    for (int i = threadIdx.x; i < 1024; i += 256) s += g_partial[i];
    float t = block_reduce_sum(s);
    if (threadIdx.x == 0) g_gval = t / (float)((size_t)Vm * Dm);
}

__global__ void quant_kernel(const float* __restrict__ w) {
    size_t i = (size_t)blockIdx.x * blockDim.x + threadIdx.x;
    if (i >= (size_t)Vm * Dm) return;
    float inv = 1.f / (g_gval + Q_EPS);
    float t = rintf(w[i] * inv);             // round-half-to-even == jnp.round
    g_twq[i] = __float2half_rn(fminf(1.f, fmaxf(-1.f, t)));  // exact: -1/0/1
}

// ---------------- host orchestration -----------------------------------------
extern "C" void kernel_launch(void* const* d_in, const int* in_sizes, int n_in,
                              void* d_out, int out_size) {
    const int*   x     = (const int*)  d_in[0];
    const float* embed = (const float*)d_in[1];
    const float* pos   = (const float*)d_in[2];
    const float* Wqkv  = (const float*)d_in[3];
    const float* bqkv  = (const float*)d_in[4];
    const float* Wo    = (const float*)d_in[5];
    const float* bo    = (const float*)d_in[6];
    const float* ln1w  = (const float*)d_in[7];
    const float* ln1b  = (const float*)d_in[8];
    const float* W1    = (const float*)d_in[9];
    const float* b1    = (const float*)d_in[10];
    const float* W2    = (const float*)d_in[11];
    const float* b2    = (const float*)d_in[12];
    const float* ln2w  = (const float*)d_in[13];
    const float* ln2b  = (const float*)d_in[14];
    const float* decw  = (const float*)d_in[15];
    const float* decb  = (const float*)d_in[16];
    float* out = (float*)d_out;

    float *h, *tmp, *qkv, *ctx, *ff;
    __half *ah, *al, *wh, *wl, *twq;
    cudaGetSymbolAddress((void**)&h,   g_h);
    cudaGetSymbolAddress((void**)&tmp, g_tmp);
    cudaGetSymbolAddress((void**)&qkv, g_qkv);
    cudaGetSymbolAddress((void**)&ctx, g_ctx);
    cudaGetSymbolAddress((void**)&ff,  g_ff);
    cudaGetSymbolAddress((void**)&ah,  g_ah);
    cudaGetSymbolAddress((void**)&al,  g_al);
    cudaGetSymbolAddress((void**)&wh,  g_wh);
    cudaGetSymbolAddress((void**)&wl,  g_wl);
    cudaGetSymbolAddress((void**)&twq, g_twq);

    // 1. embedding + positional
    embed_kernel<<<(Mm * Dm + 255) / 256, 256>>>(x, embed, pos);

    // 2. encoder layers
    for (int l = 0; l < Lm; l++) {
        const float* Wqkv_l = Wqkv + (size_t)l * 3 * Dm * Dm;
        const float* bqkv_l = bqkv + (size_t)l * 3 * Dm;
        const float* Wo_l   = Wo   + (size_t)l * Dm * Dm;
        const float* bo_l   = bo   + (size_t)l * Dm;
        const float* W1_l   = W1   + (size_t)l * FFm * Dm;
        const float* b1_l   = b1   + (size_t)l * FFm;
        const float* W2_l   = W2   + (size_t)l * Dm * FFm;
        const float* b2_l   = b2   + (size_t)l * Dm;

        // qkv = h @ Wqkv^T + bqkv      [3200, 3072]
        split_kernel<<<(Mm * Dm + 255) / 256, 256>>>(h, ah, al, Mm * Dm);
        split_kernel<<<(3 * Dm * Dm + 255) / 256, 256>>>(Wqkv_l, wh, wl, 3 * Dm * Dm);
        gemm_mma<false><<<dim3(Mm / 128, 3 * Dm / 128), 256>>>(
            ah, al, ah, wh, wh, wl, 3, bqkv_l, qkv, 3 * Dm, Dm);

        // attention -> ctx             [3200, 1024]
        attn_kernel<<<Bm * Hm, 128>>>(qkv, ctx);

        // attn_out = ctx @ Wo^T + bo
        split_kernel<<<(Mm * Dm + 255) / 256, 256>>>(ctx, ah, al, Mm * Dm);
        split_kernel<<<(Dm * Dm + 255) / 256, 256>>>(Wo_l, wh, wl, Dm * Dm);
        gemm_mma<false><<<dim3(Mm / 128, Dm / 128), 256>>>(
            ah, al, ah, wh, wh, wl, 3, bo_l, tmp, Dm, Dm);

        // h = LN(h + attn_out)
        ln_kernel<<<Mm, 256>>>(h, tmp, ln1w + (size_t)l * Dm, ln1b + (size_t)l * Dm);

        // ff = gelu(h @ W1^T + b1)     [3200, 4096]
        split_kernel<<<(Mm * Dm + 255) / 256, 256>>>(h, ah, al, Mm * Dm);
        split_kernel<<<(FFm * Dm + 255) / 256, 256>>>(W1_l, wh, wl, FFm * Dm);
        gemm_mma<true><<<dim3(Mm / 128, FFm / 128), 256>>>(
            ah, al, ah, wh, wh, wl, 3, b1_l, ff, FFm, Dm);

        // ff2 = ff @ W2^T + b2         [3200, 1024], K = 4096
        split_kernel<<<(Mm * FFm + 255) / 256, 256>>>(ff, ah, al, Mm * FFm);
        split_kernel<<<(Dm * FFm + 255) / 256, 256>>>(W2_l, wh, wl, Dm * FFm);
        gemm_mma<false><<<dim3(Mm / 128, Dm / 128), 256>>>(
            ah, al, ah, wh, wh, wl, 3, b2_l, tmp, Dm, FFm);

        // h = LN(h + ff2)
        ln_kernel<<<Mm, 256>>>(h, tmp, ln2w + (size_t)l * Dm, ln2b + (size_t)l * Dm);
    }

    // 3. ternary decoder
    absum_kernel<<<1024, 256>>>(decw);
    finalize_g_kernel<<<1, 256>>>();
    quant_kernel<<<(int)(((size_t)Vm * Dm + 255) / 256), 256>>>(decw);

    // out = h @ tw^T + dec_b           [3200, 32000]
    // 2 segments: Ah*tw + Al*tw (tw exact in fp16). grid.x = m-tiles so
    // consecutive blocks share the same tw panel (L2 reuse).
    split_kernel<<<(Mm * Dm + 255) / 256, 256>>>(h, ah, al, Mm * Dm);
    gemm_mma<false><<<dim3(Mm / 128, Vm / 128), 256>>>(
        ah, al, (const __half*)0, twq, twq, (const __half*)0,
        2, decb, out, Vm, Dm);
}

// round 5
// speedup vs baseline: 2.0991x; 1.4509x over previous
#include <cuda_runtime.h>
#include <cuda_fp16.h>
#include <math.h>
#include <stdint.h>

#define Dm   1024
#define Vm   32000
#define Hm   16
#define DHm  64
#define Bm   32
#define Sm   100
#define Mm   3200          // B*S
#define FFm  4096
#define Lm   2
#define LN_EPS 1e-5f
#define Q_EPS  1e-6f

// ---------------- scratch (static device globals; no allocation) -------------
__device__ float g_h  [Mm * Dm];
__device__ float g_tmp[Mm * Dm];
__device__ float g_qkv[Mm * 3 * Dm];
__device__ float g_ctx[Mm * Dm];
__device__ float g_ff [Mm * FFm];
__device__ __half g_ah[Mm * FFm];          // activation hi split (max 3200x4096)
__device__ __half g_al[Mm * FFm];          // activation lo split
__device__ __half g_wh[FFm * Dm];          // weight hi split (max 4096x1024)
__device__ __half g_wl[FFm * Dm];          // weight lo split
__device__ __half g_twq[(size_t)Vm * Dm];  // ternary decoder weights (exact fp16)
__device__ float g_partial[1024];
__device__ float g_gval;

// ---------------- small helpers ----------------------------------------------
__device__ __forceinline__ uint32_t smem_u32(const void* p) {
    uint32_t a;
    asm("{ .reg .u64 t; cvta.to.shared.u64 t, %1; cvt.u32.u64 %0, t; }" : "=r"(a) : "l"(p));
    return a;
}

__device__ __forceinline__ float gelu_exact(float x) {
    return 0.5f * x * (1.0f + erff(x * 0.70710678118654752440f));
}

__device__ __forceinline__ float block_reduce_sum(float v) {
    __shared__ float red[32];
    int lane = threadIdx.x & 31;
    int wid  = threadIdx.x >> 5;
#pragma unroll
    for (int o = 16; o > 0; o >>= 1) v += __shfl_xor_sync(0xffffffffu, v, o);
    if (lane == 0) red[wid] = v;
    __syncthreads();
    int nw = blockDim.x >> 5;
    float s = (threadIdx.x < nw) ? red[threadIdx.x] : 0.f;
    if (wid == 0) {
#pragma unroll
        for (int o = 16; o > 0; o >>= 1) s += __shfl_xor_sync(0xffffffffu, s, o);
        if (lane == 0) red[0] = s;
    }
    __syncthreads();
    float r = red[0];
    __syncthreads();
    return r;
}

// ---------------- elementwise kernels -----------------------------------------
__global__ void embed_kernel(const int* __restrict__ x,
                             const float* __restrict__ embed,
                             const float* __restrict__ pos) {
    int i = blockIdx.x * blockDim.x + threadIdx.x;
    if (i >= Mm * Dm) return;
    int m = i / Dm, d = i - m * Dm;
    int s = m % Sm;
    g_h[i] = embed[(size_t)x[m] * Dm + d] + pos[s * Dm + d];
}

// fp32 -> (hi, lo) fp16 split
__global__ void split_kernel(const float* __restrict__ src,
                             __half* __restrict__ hi,
                             __half* __restrict__ lo, int n) {
    int i = blockIdx.x * blockDim.x + threadIdx.x;
    if (i >= n) return;
    float x = src[i];
    __half h = __float2half_rn(x);
    hi[i] = h;
    lo[i] = __float2half_rn(x - __half2float(h));
}

// ---------------- mma.sync GEMM -----------------------------------------------
// C[M,N] = sum_seg A_s[M,K] * B_s[N,K]^T + bias (opt GELU)
// CTA tile 128x256, BK=32, 256 threads (8 warps 2x4), warp tile 64x64.
// 3-stage cp.async pipeline, one __syncthreads per BK iter.
// smem rows padded to 40 halves (80B) -> conflict-free ldmatrix.

#define BMt 128
#define BNt 256
#define SROW 40                    // halves per smem row (32 data + 8 pad)
#define STAGES 3
#define A_STAGE (BMt * SROW)       // halves
#define B_STAGE (BNt * SROW)
#define GEMM_SMEM_BYTES ((STAGES * (A_STAGE + B_STAGE)) * 2)

__device__ __forceinline__ void cp_async16(uint32_t dst, const void* src) {
    asm volatile("cp.async.cg.shared.global [%0], [%1], 16;" :: "r"(dst), "l"(src));
}
__device__ __forceinline__ void ldsm_x4(uint32_t* r, uint32_t addr) {
    asm volatile("ldmatrix.sync.aligned.m8n8.x4.shared.b16 {%0,%1,%2,%3}, [%4];"
                 : "=r"(r[0]), "=r"(r[1]), "=r"(r[2]), "=r"(r[3]) : "r"(addr));
}
__device__ __forceinline__ void mma_16816(float* d, const uint32_t* a, uint32_t b0, uint32_t b1) {
    asm volatile(
        "mma.sync.aligned.m16n8k16.row.col.f32.f16.f16.f32 "
        "{%0,%1,%2,%3}, {%4,%5,%6,%7}, {%8,%9}, {%0,%1,%2,%3};"
        : "+f"(d[0]), "+f"(d[1]), "+f"(d[2]), "+f"(d[3])
        : "r"(a[0]), "r"(a[1]), "r"(a[2]), "r"(a[3]), "r"(b0), "r"(b1));
}

#define PREFETCH(it, buf)                                                        \
    {                                                                            \
        int seg_ = (it) / tilesPerSeg;                                           \
        int k0_  = ((it) - seg_ * tilesPerSeg) << 5;                             \
        const __half* Ap_ = As[seg_] + (size_t)(mt * BMt) * K + k0_;             \
        const __half* Bp_ = Bs[seg_] + (size_t)(nt * BNt) * K + k0_;             \
        __half* dA_ = sA + (buf) * A_STAGE;                                      \
        __half* dB_ = sB + (buf) * B_STAGE;                                      \
        _Pragma("unroll")                                                        \
        for (int j_ = 0; j_ < 2; j_++) {                                         \
            int c_ = tid + 256 * j_;                                             \
            int row_ = c_ >> 2, ch_ = (c_ & 3) * 8;                              \
            cp_async16(smem_u32(dA_ + row_ * SROW + ch_),                        \
                       Ap_ + (size_t)row_ * K + ch_);                            \
        }                                                                        \
        _Pragma("unroll")                                                        \
        for (int j_ = 0; j_ < 4; j_++) {                                         \
            int c_ = tid + 256 * j_;                                             \
            int row_ = c_ >> 2, ch_ = (c_ & 3) * 8;                              \
            cp_async16(smem_u32(dB_ + row_ * SROW + ch_),                        \
                       Bp_ + (size_t)row_ * K + ch_);                            \
        }                                                                        \
    }

template<bool GELU>
__global__ __launch_bounds__(256, 1) void gemm_mma(
    const __half* __restrict__ A0, const __half* __restrict__ A1,
    const __half* __restrict__ A2,
    const __half* __restrict__ B0, const __half* __restrict__ B1,
    const __half* __restrict__ B2,
    int nseg, const float* __restrict__ bias, float* __restrict__ C,
    int N, int K)
{
    extern __shared__ __align__(16) __half smem[];
    __half* sA = smem;                       // [STAGES][A_STAGE]
    __half* sB = smem + STAGES * A_STAGE;    // [STAGES][B_STAGE]

    const int tid = threadIdx.x;
    const int wid = tid >> 5;
    const int lane = tid & 31;
    const int warp_m = wid & 1;        // 0..1 (64 rows each)
    const int warp_n = wid >> 1;       // 0..3 (64 cols each)
    const int mt = blockIdx.x;
    const int nt = blockIdx.y;

    const __half* As[3] = {A0, A1, A2};
    const __half* Bs[3] = {B0, B1, B2};
    const int tilesPerSeg = K >> 5;          // K/32
    const int T = nseg * tilesPerSeg;

    float acc[4][8][4];
#pragma unroll
    for (int i = 0; i < 4; i++)
#pragma unroll
        for (int j = 0; j < 8; j++)
#pragma unroll
            for (int r = 0; r < 4; r++) acc[i][j][r] = 0.f;

    // ldmatrix lane addressing
    const int q = lane >> 3, lr = lane & 7;
    const int a_row_base = warp_m * 64 + (q & 1) * 8 + lr;   // + mi*16
    const int a_kq = (q >> 1) * 8;
    const int b_row_base = warp_n * 64 + (q >> 1) * 8 + lr;  // + jp*16
    const int b_kq = (q & 1) * 8;

    PREFETCH(0, 0);
    asm volatile("cp.async.commit_group;" ::: "memory");
    PREFETCH(1, 1);
    asm volatile("cp.async.commit_group;" ::: "memory");

    for (int it = 0; it < T; it++) {
        asm volatile("cp.async.wait_group %0;" :: "n"(STAGES - 2) : "memory");
        __syncthreads();

        const int pf = it + STAGES - 1;
        if (pf < T) { PREFETCH(pf, pf % STAGES); }
        asm volatile("cp.async.commit_group;" ::: "memory");

        const __half* sAb = sA + (it % STAGES) * A_STAGE;
        const __half* sBb = sB + (it % STAGES) * B_STAGE;
#pragma unroll
        for (int ks = 0; ks < 2; ks++) {
            uint32_t a[4][4];
#pragma unroll
            for (int mi = 0; mi < 4; mi++)
                ldsm_x4(a[mi], smem_u32(&sAb[(a_row_base + mi * 16) * SROW + ks * 16 + a_kq]));
            uint32_t b[4][4];
#pragma unroll
            for (int jp = 0; jp < 4; jp++)
                ldsm_x4(b[jp], smem_u32(&sBb[(b_row_base + jp * 16) * SROW + ks * 16 + b_kq]));
#pragma unroll
            for (int mi = 0; mi < 4; mi++)
#pragma unroll
                for (int nj = 0; nj < 8; nj++) {
                    int jp = nj >> 1, h = nj & 1;
                    mma_16816(acc[mi][nj], a[mi], b[jp][h * 2], b[jp][h * 2 + 1]);
                }
        }
    }

    // epilogue
    const int g  = lane >> 2;
    const int tg = lane & 3;
#pragma unroll
    for (int mi = 0; mi < 4; mi++) {
#pragma unroll
        for (int nj = 0; nj < 8; nj++) {
            int row = mt * BMt + warp_m * 64 + mi * 16 + g;
            int col = nt * BNt + warp_n * 64 + nj * 8 + tg * 2;
            float b0 = bias[col], b1 = bias[col + 1];
            float v0 = acc[mi][nj][0] + b0;
            float v1 = acc[mi][nj][1] + b1;
            float v2 = acc[mi][nj][2] + b0;
            float v3 = acc[mi][nj][3] + b1;
            if (GELU) { v0 = gelu_exact(v0); v1 = gelu_exact(v1);
                        v2 = gelu_exact(v2); v3 = gelu_exact(v3); }
            *(float2*)(C + (size_t)row * N + col)       = make_float2(v0, v1);
            *(float2*)(C + (size_t)(row + 8) * N + col) = make_float2(v2, v3);
        }
    }
}

// ---------------- fused attention: one block per (b,h) -----------------------
__global__ __launch_bounds__(128) void attn_kernel(const float* __restrict__ qkv,
                                                   float* __restrict__ ctx) {
    __shared__ float Ks[Sm][DHm];
    __shared__ float Vs[Sm][DHm];
    const int h = blockIdx.x % Hm;
    const int b = blockIdx.x / Hm;
    const int base = b * Sm;
    const int tid = threadIdx.x;

    for (int idx = tid; idx < Sm * DHm; idx += blockDim.x) {
        int r = idx / DHm, c = idx - r * DHm;
        size_t row = (size_t)(base + r) * (3 * Dm);
        Ks[r][c] = qkv[row + Dm     + h * DHm + c];
        Vs[r][c] = qkv[row + 2 * Dm + h * DHm + c];
    }
    __syncthreads();

    if (tid < Sm) {
        float q[DHm];
        const float* qp = qkv + (size_t)(base + tid) * (3 * Dm) + h * DHm;
#pragma unroll
        for (int d = 0; d < DHm; d++) q[d] = qp[d];

        float p[Sm];
        float mx = -1e30f;
        for (int k = 0; k < Sm; k++) {
            float s = 0.f;
#pragma unroll
            for (int d = 0; d < DHm; d++) s += q[d] * Ks[k][d];
            s *= 0.125f;
            p[k] = s;
            mx = fmaxf(mx, s);
        }
        float sum = 0.f;
        for (int k = 0; k < Sm; k++) { p[k] = expf(p[k] - mx); sum += p[k]; }
        float inv = 1.f / sum;

        float* cp = ctx + (size_t)(base + tid) * Dm + h * DHm;
        for (int d = 0; d < DHm; d++) {
            float a = 0.f;
            for (int k = 0; k < Sm; k++) a += p[k] * Vs[k][d];
            cp[d] = a * inv;
        }
    }
}

// ---------------- residual + layernorm (in place on g_h) ---------------------
__global__ __launch_bounds__(256) void ln_kernel(float* __restrict__ h,
                                                 const float* __restrict__ delta,
                                                 const float* __restrict__ w,
                                                 const float* __restrict__ bias) {
    const int row = blockIdx.x;
    const size_t off = (size_t)row * Dm;
    float v[4];
    float s = 0.f;
#pragma unroll
    for (int i = 0; i < 4; i++) {
        int c = threadIdx.x + i * 256;
        v[i] = h[off + c] + delta[off + c];
        s += v[i];
    }
    float mean = block_reduce_sum(s) * (1.f / Dm);
    float s2 = 0.f;
#pragma unroll
    for (int i = 0; i < 4; i++) { float d = v[i] - mean; s2 += d * d; }
    float var = block_reduce_sum(s2) * (1.f / Dm);
    float inv = rsqrtf(var + LN_EPS);
#pragma unroll
    for (int i = 0; i < 4; i++) {
        int c = threadIdx.x + i * 256;
        h[off + c] = (v[i] - mean) * inv * w[c] + bias[c];
    }
}

// ---------------- decoder weight scale + quantize ----------------------------
__global__ __launch_bounds__(256) void absum_kernel(const float* __restrict__ w) {
    float s = 0.f;
    const size_t total = (size_t)Vm * Dm;
    for (size_t i = (size_t)blockIdx.x * blockDim.x + threadIdx.x; i < total;
         i += (size_t)gridDim.x * blockDim.x)
        s += fabsf(w[i]);
    float bs = block_reduce_sum(s);
    if (threadIdx.x == 0) g_partial[blockIdx.x] = bs;
}

__global__ __launch_bounds__(256) void finalize_g_kernel() {
    float s = 0.f;
    for (int i = threadIdx.x; i < 1024; i += 256) s += g_partial[i];
    float t = block_reduce_sum(s);
    if (threadIdx.x == 0) g_gval = t / (float)((size_t)Vm * Dm);
}

__global__ void quant_kernel(const float* __restrict__ w) {
    size_t i = (size_t)blockIdx.x * blockDim.x + threadIdx.x;
    if (i >= (size_t)Vm * Dm) return;
    float inv = 1.f / (g_gval + Q_EPS);
    float t = rintf(w[i] * inv);             // round-half-to-even == jnp.round
    g_twq[i] = __float2half_rn(fminf(1.f, fmaxf(-1.f, t)));  // exact: -1/0/1
}

// ---------------- host orchestration -----------------------------------------
extern "C" void kernel_launch(void* const* d_in, const int* in_sizes, int n_in,
                              void* d_out, int out_size) {
    const int*   x     = (const int*)  d_in[0];
    const float* embed = (const float*)d_in[1];
    const float* pos   = (const float*)d_in[2];
    const float* Wqkv  = (const float*)d_in[3];
    const float* bqkv  = (const float*)d_in[4];
    const float* Wo    = (const float*)d_in[5];
    const float* bo    = (const float*)d_in[6];
    const float* ln1w  = (const float*)d_in[7];
    const float* ln1b  = (const float*)d_in[8];
    const float* W1    = (const float*)d_in[9];
    const float* b1    = (const float*)d_in[10];
    const float* W2    = (const float*)d_in[11];
    const float* b2    = (const float*)d_in[12];
    const float* ln2w  = (const float*)d_in[13];
    const float* ln2b  = (const float*)d_in[14];
    const float* decw  = (const float*)d_in[15];
    const float* decb  = (const float*)d_in[16];
    float* out = (float*)d_out;

    float *h, *tmp, *qkv, *ctx, *ff;
    __half *ah, *al, *wh, *wl, *twq;
    cudaGetSymbolAddress((void**)&h,   g_h);
    cudaGetSymbolAddress((void**)&tmp, g_tmp);
    cudaGetSymbolAddress((void**)&qkv, g_qkv);
    cudaGetSymbolAddress((void**)&ctx, g_ctx);
    cudaGetSymbolAddress((void**)&ff,  g_ff);
    cudaGetSymbolAddress((void**)&ah,  g_ah);
    cudaGetSymbolAddress((void**)&al,  g_al);
    cudaGetSymbolAddress((void**)&wh,  g_wh);
    cudaGetSymbolAddress((void**)&wl,  g_wl);
    cudaGetSymbolAddress((void**)&twq, g_twq);

    // allow 90KB dynamic smem for the GEMM kernels
    cudaFuncSetAttribute(gemm_mma<false>, cudaFuncAttributeMaxDynamicSharedMemorySize, GEMM_SMEM_BYTES);
    cudaFuncSetAttribute(gemm_mma<true>,  cudaFuncAttributeMaxDynamicSharedMemorySize, GEMM_SMEM_BYTES);

    // 1. embedding + positional
    embed_kernel<<<(Mm * Dm + 255) / 256, 256>>>(x, embed, pos);

    // 2. encoder layers
    for (int l = 0; l < Lm; l++) {
        const float* Wqkv_l = Wqkv + (size_t)l * 3 * Dm * Dm;
        const float* bqkv_l = bqkv + (size_t)l * 3 * Dm;
        const float* Wo_l   = Wo   + (size_t)l * Dm * Dm;
        const float* bo_l   = bo   + (size_t)l * Dm;
        const float* W1_l   = W1   + (size_t)l * FFm * Dm;
        const float* b1_l   = b1   + (size_t)l * FFm;
        const float* W2_l   = W2   + (size_t)l * Dm * FFm;
        const float* b2_l   = b2   + (size_t)l * Dm;

        // qkv = h @ Wqkv^T + bqkv      [3200, 3072]
        split_kernel<<<(Mm * Dm + 255) / 256, 256>>>(h, ah, al, Mm * Dm);
        split_kernel<<<(3 * Dm * Dm + 255) / 256, 256>>>(Wqkv_l, wh, wl, 3 * Dm * Dm);
        gemm_mma<false><<<dim3(Mm / BMt, 3 * Dm / BNt), 256, GEMM_SMEM_BYTES>>>(
            ah, al, ah, wh, wh, wl, 3, bqkv_l, qkv, 3 * Dm, Dm);

        // attention -> ctx             [3200, 1024]
        attn_kernel<<<Bm * Hm, 128>>>(qkv, ctx);

        // attn_out = ctx @ Wo^T + bo
        split_kernel<<<(Mm * Dm + 255) / 256, 256>>>(ctx, ah, al, Mm * Dm);
        split_kernel<<<(Dm * Dm + 255) / 256, 256>>>(Wo_l, wh, wl, Dm * Dm);
        gemm_mma<false><<<dim3(Mm / BMt, Dm / BNt), 256, GEMM_SMEM_BYTES>>>(
            ah, al, ah, wh, wh, wl, 3, bo_l, tmp, Dm, Dm);

        // h = LN(h + attn_out)
        ln_kernel<<<Mm, 256>>>(h, tmp, ln1w + (size_t)l * Dm, ln1b + (size_t)l * Dm);

        // ff = gelu(h @ W1^T + b1)     [3200, 4096]
        split_kernel<<<(Mm * Dm + 255) / 256, 256>>>(h, ah, al, Mm * Dm);
        split_kernel<<<(FFm * Dm + 255) / 256, 256>>>(W1_l, wh, wl, FFm * Dm);
        gemm_mma<true><<<dim3(Mm / BMt, FFm / BNt), 256, GEMM_SMEM_BYTES>>>(
            ah, al, ah, wh, wh, wl, 3, b1_l, ff, FFm, Dm);

        // ff2 = ff @ W2^T + b2         [3200, 1024], K = 4096
        split_kernel<<<(Mm * FFm + 255) / 256, 256>>>(ff, ah, al, Mm * FFm);
        split_kernel<<<(Dm * FFm + 255) / 256, 256>>>(W2_l, wh, wl, Dm * FFm);
        gemm_mma<false><<<dim3(Mm / BMt, Dm / BNt), 256, GEMM_SMEM_BYTES>>>(
            ah, al, ah, wh, wh, wl, 3, b2_l, tmp, Dm, FFm);

        // h = LN(h + ff2)
        ln_kernel<<<Mm, 256>>>(h, tmp, ln2w + (size_t)l * Dm, ln2b + (size_t)l * Dm);
    }

    // 3. ternary decoder
    absum_kernel<<<1024, 256>>>(decw);
    finalize_g_kernel<<<1, 256>>>();
    quant_kernel<<<(int)(((size_t)Vm * Dm + 255) / 256), 256>>>(decw);

    // out = h @ tw^T + dec_b           [3200, 32000]
    // 2 segments: Ah*tw + Al*tw (tw exact in fp16). grid.x = m-tiles so
    // consecutive blocks share the same tw panel (L2 reuse).
    split_kernel<<<(Mm * Dm + 255) / 256, 256>>>(h, ah, al, Mm * Dm);
    gemm_mma<false><<<dim3(Mm / BMt, Vm / BNt), 256, GEMM_SMEM_BYTES>>>(
        ah, al, (const __half*)0, twq, twq, (const __half*)0,
        2, decb, out, Vm, Dm);
}

// round 6
// speedup vs baseline: 2.6184x; 1.2474x over previous
#include <cuda_runtime.h>
#include <cuda_fp16.h>
#include <math.h>
#include <stdint.h>

#define Dm   1024
#define Vm   32000
#define Hm   16
#define DHm  64
#define Bm   32
#define Sm   100
#define Mm   3200          // B*S
#define FFm  4096
#define Lm   2
#define LN_EPS 1e-5f
#define Q_EPS  1e-6f

// ---------------- scratch (static device globals; no allocation) -------------
__device__ float g_h  [Mm * Dm];
__device__ float g_tmp[Mm * Dm];
__device__ float g_qkv[Mm * 3 * Dm];
__device__ float g_ctx[Mm * Dm];
__device__ float g_ff [Mm * FFm];
__device__ __half g_ah[Mm * FFm];          // activation hi split (max 3200x4096)
__device__ __half g_al[Mm * FFm];          // activation lo split
__device__ __half g_wh[FFm * Dm];          // weight hi split (max 4096x1024)
__device__ __half g_wl[FFm * Dm];          // weight lo split
__device__ __half g_twq[(size_t)Vm * Dm];  // ternary decoder weights (exact fp16)
__device__ float g_partial[1024];
__device__ float g_gval;

// ---------------- small helpers ----------------------------------------------
__device__ __forceinline__ uint32_t smem_u32(const void* p) {
    uint32_t a;
    asm("{ .reg .u64 t; cvta.to.shared.u64 t, %1; cvt.u32.u64 %0, t; }" : "=r"(a) : "l"(p));
    return a;
}

__device__ __forceinline__ float gelu_exact(float x) {
    return 0.5f * x * (1.0f + erff(x * 0.70710678118654752440f));
}

__device__ __forceinline__ float block_reduce_sum(float v) {
    __shared__ float red[32];
    int lane = threadIdx.x & 31;
    int wid  = threadIdx.x >> 5;
#pragma unroll
    for (int o = 16; o > 0; o >>= 1) v += __shfl_xor_sync(0xffffffffu, v, o);
    if (lane == 0) red[wid] = v;
    __syncthreads();
    int nw = blockDim.x >> 5;
    float s = (threadIdx.x < nw) ? red[threadIdx.x] : 0.f;
    if (wid == 0) {
#pragma unroll
        for (int o = 16; o > 0; o >>= 1) s += __shfl_xor_sync(0xffffffffu, s, o);
        if (lane == 0) red[0] = s;
    }
    __syncthreads();
    float r = red[0];
    __syncthreads();
    return r;
}

// ---------------- elementwise kernels -----------------------------------------
__global__ void embed_kernel(const int* __restrict__ x,
                             const float* __restrict__ embed,
                             const float* __restrict__ pos) {
    int i = blockIdx.x * blockDim.x + threadIdx.x;
    if (i >= Mm * Dm) return;
    int m = i / Dm, d = i - m * Dm;
    int s = m % Sm;
    g_h[i] = embed[(size_t)x[m] * Dm + d] + pos[s * Dm + d];
}

// fp32 -> (hi, lo) fp16 split
__global__ void split_kernel(const float* __restrict__ src,
                             __half* __restrict__ hi,
                             __half* __restrict__ lo, int n) {
    int i = blockIdx.x * blockDim.x + threadIdx.x;
    if (i >= n) return;
    float x = src[i];
    __half h = __float2half_rn(x);
    hi[i] = h;
    lo[i] = __float2half_rn(x - __half2float(h));
}

// ---------------- mma.sync GEMM -----------------------------------------------
// C[M,N] = sum_seg A_s[M,K] * B_s[N,K]^T + bias (opt GELU)
// CTA tile 128x128, BK=32, 128 threads (4 warps 2x2), warp tile 64x64.
// 4-stage cp.async pipeline, one __syncthreads per BK iter, 2 CTAs/SM.
// smem rows padded to 40 halves (80B) -> conflict-free ldmatrix.

#define BMt 128
#define BNt 128
#define NTHREADS 128
#define SROW 40                    // halves per smem row (32 data + 8 pad)
#define STAGES 4
#define A_STAGE (BMt * SROW)       // halves
#define B_STAGE (BNt * SROW)
#define GEMM_SMEM_BYTES ((STAGES * (A_STAGE + B_STAGE)) * 2)

__device__ __forceinline__ void cp_async16(uint32_t dst, const void* src) {
    asm volatile("cp.async.cg.shared.global [%0], [%1], 16;" :: "r"(dst), "l"(src));
}
__device__ __forceinline__ void ldsm_x4(uint32_t* r, uint32_t addr) {
    asm volatile("ldmatrix.sync.aligned.m8n8.x4.shared.b16 {%0,%1,%2,%3}, [%4];"
                 : "=r"(r[0]), "=r"(r[1]), "=r"(r[2]), "=r"(r[3]) : "r"(addr));
}
__device__ __forceinline__ void mma_16816(float* d, const uint32_t* a, uint32_t b0, uint32_t b1) {
    asm volatile(
        "mma.sync.aligned.m16n8k16.row.col.f32.f16.f16.f32 "
        "{%0,%1,%2,%3}, {%4,%5,%6,%7}, {%8,%9}, {%0,%1,%2,%3};"
        : "+f"(d[0]), "+f"(d[1]), "+f"(d[2]), "+f"(d[3])
        : "r"(a[0]), "r"(a[1]), "r"(a[2]), "r"(a[3]), "r"(b0), "r"(b1));
}

#define PREFETCH(it, buf)                                                        \
    {                                                                            \
        int seg_ = (it) / tilesPerSeg;                                           \
        int k0_  = ((it) - seg_ * tilesPerSeg) << 5;                             \
        const __half* Ap_ = As[seg_] + (size_t)(mt * BMt) * K + k0_;             \
        const __half* Bp_ = Bs[seg_] + (size_t)(nt * BNt) * K + k0_;             \
        __half* dA_ = sA + (buf) * A_STAGE;                                      \
        __half* dB_ = sB + (buf) * B_STAGE;                                      \
        _Pragma("unroll")                                                        \
        for (int j_ = 0; j_ < 4; j_++) {                                         \
            int c_ = tid + NTHREADS * j_;                                        \
            int row_ = c_ >> 2, ch_ = (c_ & 3) * 8;                              \
            cp_async16(smem_u32(dA_ + row_ * SROW + ch_),                        \
                       Ap_ + (size_t)row_ * K + ch_);                            \
        }                                                                        \
        _Pragma("unroll")                                                        \
        for (int j_ = 0; j_ < 4; j_++) {                                         \
            int c_ = tid + NTHREADS * j_;                                        \
            int row_ = c_ >> 2, ch_ = (c_ & 3) * 8;                              \
            cp_async16(smem_u32(dB_ + row_ * SROW + ch_),                        \
                       Bp_ + (size_t)row_ * K + ch_);                            \
        }                                                                        \
    }

template<bool GELU>
__global__ __launch_bounds__(NTHREADS, 2) void gemm_mma(
    const __half* __restrict__ A0, const __half* __restrict__ A1,
    const __half* __restrict__ A2,
    const __half* __restrict__ B0, const __half* __restrict__ B1,
    const __half* __restrict__ B2,
    int nseg, const float* __restrict__ bias, float* __restrict__ C,
    int N, int K)
{
    extern __shared__ __align__(16) __half smem[];
    __half* sA = smem;                       // [STAGES][A_STAGE]
    __half* sB = smem + STAGES * A_STAGE;    // [STAGES][B_STAGE]

    const int tid = threadIdx.x;
    const int wid = tid >> 5;
    const int lane = tid & 31;
    const int warp_m = wid & 1;        // 0..1 (64 rows each)
    const int warp_n = wid >> 1;       // 0..1 (64 cols each)
    const int mt = blockIdx.x;
    const int nt = blockIdx.y;

    const __half* As[3] = {A0, A1, A2};
    const __half* Bs[3] = {B0, B1, B2};
    const int tilesPerSeg = K >> 5;          // K/32
    const int T = nseg * tilesPerSeg;

    float acc[4][8][4];
#pragma unroll
    for (int i = 0; i < 4; i++)
#pragma unroll
        for (int j = 0; j < 8; j++)
#pragma unroll
            for (int r = 0; r < 4; r++) acc[i][j][r] = 0.f;

    // ldmatrix lane addressing
    const int q = lane >> 3, lr = lane & 7;
    const int a_row_base = warp_m * 64 + (q & 1) * 8 + lr;   // + mi*16
    const int a_kq = (q >> 1) * 8;
    const int b_row_base = warp_n * 64 + (q >> 1) * 8 + lr;  // + jp*16
    const int b_kq = (q & 1) * 8;

    PREFETCH(0, 0);
    asm volatile("cp.async.commit_group;" ::: "memory");
    PREFETCH(1, 1);
    asm volatile("cp.async.commit_group;" ::: "memory");
    PREFETCH(2, 2);
    asm volatile("cp.async.commit_group;" ::: "memory");

    for (int it = 0; it < T; it++) {
        asm volatile("cp.async.wait_group %0;" :: "n"(STAGES - 2) : "memory");
        __syncthreads();

        const int pf = it + STAGES - 1;
        if (pf < T) { PREFETCH(pf, pf % STAGES); }
        asm volatile("cp.async.commit_group;" ::: "memory");

        const __half* sAb = sA + (it % STAGES) * A_STAGE;
        const __half* sBb = sB + (it % STAGES) * B_STAGE;
#pragma unroll
        for (int ks = 0; ks < 2; ks++) {
            uint32_t a[4][4];
#pragma unroll
            for (int mi = 0; mi < 4; mi++)
                ldsm_x4(a[mi], smem_u32(&sAb[(a_row_base + mi * 16) * SROW + ks * 16 + a_kq]));
            uint32_t b[4][4];
#pragma unroll
            for (int jp = 0; jp < 4; jp++)
                ldsm_x4(b[jp], smem_u32(&sBb[(b_row_base + jp * 16) * SROW + ks * 16 + b_kq]));
#pragma unroll
            for (int mi = 0; mi < 4; mi++)
#pragma unroll
                for (int nj = 0; nj < 8; nj++) {
                    int jp = nj >> 1, h = nj & 1;
                    mma_16816(acc[mi][nj], a[mi], b[jp][h * 2], b[jp][h * 2 + 1]);
                }
        }
    }

    // epilogue
    const int g  = lane >> 2;
    const int tg = lane & 3;
#pragma unroll
    for (int mi = 0; mi < 4; mi++) {
#pragma unroll
        for (int nj = 0; nj < 8; nj++) {
            int row = mt * BMt + warp_m * 64 + mi * 16 + g;
            int col = nt * BNt + warp_n * 64 + nj * 8 + tg * 2;
            float b0 = bias[col], b1 = bias[col + 1];
            float v0 = acc[mi][nj][0] + b0;
            float v1 = acc[mi][nj][1] + b1;
            float v2 = acc[mi][nj][2] + b0;
            float v3 = acc[mi][nj][3] + b1;
            if (GELU) { v0 = gelu_exact(v0); v1 = gelu_exact(v1);
                        v2 = gelu_exact(v2); v3 = gelu_exact(v3); }
            *(float2*)(C + (size_t)row * N + col)       = make_float2(v0, v1);
            *(float2*)(C + (size_t)(row + 8) * N + col) = make_float2(v2, v3);
        }
    }
}

// ---------------- fused attention: one block per (b,h) -----------------------
__global__ __launch_bounds__(128) void attn_kernel(const float* __restrict__ qkv,
                                                   float* __restrict__ ctx) {
    __shared__ float Ks[Sm][DHm];
    __shared__ float Vs[Sm][DHm];
    const int h = blockIdx.x % Hm;
    const int b = blockIdx.x / Hm;
    const int base = b * Sm;
    const int tid = threadIdx.x;

    for (int idx = tid; idx < Sm * DHm; idx += blockDim.x) {
        int r = idx / DHm, c = idx - r * DHm;
        size_t row = (size_t)(base + r) * (3 * Dm);
        Ks[r][c] = qkv[row + Dm     + h * DHm + c];
        Vs[r][c] = qkv[row + 2 * Dm + h * DHm + c];
    }
    __syncthreads();

    if (tid < Sm) {
        float q[DHm];
        const float* qp = qkv + (size_t)(base + tid) * (3 * Dm) + h * DHm;
#pragma unroll
        for (int d = 0; d < DHm; d++) q[d] = qp[d];

        float p[Sm];
        float mx = -1e30f;
        for (int k = 0; k < Sm; k++) {
            float s = 0.f;
#pragma unroll
            for (int d = 0; d < DHm; d++) s += q[d] * Ks[k][d];
            s *= 0.125f;
            p[k] = s;
            mx = fmaxf(mx, s);
        }
        float sum = 0.f;
        for (int k = 0; k < Sm; k++) { p[k] = expf(p[k] - mx); sum += p[k]; }
        float inv = 1.f / sum;

        float* cp = ctx + (size_t)(base + tid) * Dm + h * DHm;
        for (int d = 0; d < DHm; d++) {
            float a = 0.f;
            for (int k = 0; k < Sm; k++) a += p[k] * Vs[k][d];
            cp[d] = a * inv;
        }
    }
}

// ---------------- residual + layernorm (in place on g_h) ---------------------
__global__ __launch_bounds__(256) void ln_kernel(float* __restrict__ h,
                                                 const float* __restrict__ delta,
                                                 const float* __restrict__ w,
                                                 const float* __restrict__ bias) {
    const int row = blockIdx.x;
    const size_t off = (size_t)row * Dm;
    float v[4];
    float s = 0.f;
#pragma unroll
    for (int i = 0; i < 4; i++) {
        int c = threadIdx.x + i * 256;
        v[i] = h[off + c] + delta[off + c];
        s += v[i];
    }
    float mean = block_reduce_sum(s) * (1.f / Dm);
    float s2 = 0.f;
#pragma unroll
    for (int i = 0; i < 4; i++) { float d = v[i] - mean; s2 += d * d; }
    float var = block_reduce_sum(s2) * (1.f / Dm);
    float inv = rsqrtf(var + LN_EPS);
#pragma unroll
    for (int i = 0; i < 4; i++) {
        int c = threadIdx.x + i * 256;
        h[off + c] = (v[i] - mean) * inv * w[c] + bias[c];
    }
}

// ---------------- decoder weight scale + quantize ----------------------------
__global__ __launch_bounds__(256) void absum_kernel(const float* __restrict__ w) {
    float s = 0.f;
    const size_t total = (size_t)Vm * Dm;
    for (size_t i = (size_t)blockIdx.x * blockDim.x + threadIdx.x; i < total;
         i += (size_t)gridDim.x * blockDim.x)
        s += fabsf(w[i]);
    float bs = block_reduce_sum(s);
    if (threadIdx.x == 0) g_partial[blockIdx.x] = bs;
}

__global__ __launch_bounds__(256) void finalize_g_kernel() {
    float s = 0.f;
    for (int i = threadIdx.x; i < 1024; i += 256) s += g_partial[i];
    float t = block_reduce_sum(s);
    if (threadIdx.x == 0) g_gval = t / (float)((size_t)Vm * Dm);
}

__global__ void quant_kernel(const float* __restrict__ w) {
    size_t i = (size_t)blockIdx.x * blockDim.x + threadIdx.x;
    if (i >= (size_t)Vm * Dm) return;
    float inv = 1.f / (g_gval + Q_EPS);
    float t = rintf(w[i] * inv);             // round-half-to-even == jnp.round
    g_twq[i] = __float2half_rn(fminf(1.f, fmaxf(-1.f, t)));  // exact: -1/0/1
}

// ---------------- host orchestration -----------------------------------------
extern "C" void kernel_launch(void* const* d_in, const int* in_sizes, int n_in,
                              void* d_out, int out_size) {
    const int*   x     = (const int*)  d_in[0];
    const float* embed = (const float*)d_in[1];
    const float* pos   = (const float*)d_in[2];
    const float* Wqkv  = (const float*)d_in[3];
    const float* bqkv  = (const float*)d_in[4];
    const float* Wo    = (const float*)d_in[5];
    const float* bo    = (const float*)d_in[6];
    const float* ln1w  = (const float*)d_in[7];
    const float* ln1b  = (const float*)d_in[8];
    const float* W1    = (const float*)d_in[9];
    const float* b1    = (const float*)d_in[10];
    const float* W2    = (const float*)d_in[11];
    const float* b2    = (const float*)d_in[12];
    const float* ln2w  = (const float*)d_in[13];
    const float* ln2b  = (const float*)d_in[14];
    const float* decw  = (const float*)d_in[15];
    const float* decb  = (const float*)d_in[16];
    float* out = (float*)d_out;

    float *h, *tmp, *qkv, *ctx, *ff;
    __half *ah, *al, *wh, *wl, *twq;
    cudaGetSymbolAddress((void**)&h,   g_h);
    cudaGetSymbolAddress((void**)&tmp, g_tmp);
    cudaGetSymbolAddress((void**)&qkv, g_qkv);
    cudaGetSymbolAddress((void**)&ctx, g_ctx);
    cudaGetSymbolAddress((void**)&ff,  g_ff);
    cudaGetSymbolAddress((void**)&ah,  g_ah);
    cudaGetSymbolAddress((void**)&al,  g_al);
    cudaGetSymbolAddress((void**)&wh,  g_wh);
    cudaGetSymbolAddress((void**)&wl,  g_wl);
    cudaGetSymbolAddress((void**)&twq, g_twq);

    cudaFuncSetAttribute(gemm_mma<false>, cudaFuncAttributeMaxDynamicSharedMemorySize, GEMM_SMEM_BYTES);
    cudaFuncSetAttribute(gemm_mma<true>,  cudaFuncAttributeMaxDynamicSharedMemorySize, GEMM_SMEM_BYTES);

    // 1. embedding + positional
    embed_kernel<<<(Mm * Dm + 255) / 256, 256>>>(x, embed, pos);

    // 2. encoder layers
    for (int l = 0; l < Lm; l++) {
        const float* Wqkv_l = Wqkv + (size_t)l * 3 * Dm * Dm;
        const float* bqkv_l = bqkv + (size_t)l * 3 * Dm;
        const float* Wo_l   = Wo   + (size_t)l * Dm * Dm;
        const float* bo_l   = bo   + (size_t)l * Dm;
        const float* W1_l   = W1   + (size_t)l * FFm * Dm;
        const float* b1_l   = b1   + (size_t)l * FFm;
        const float* W2_l   = W2   + (size_t)l * Dm * FFm;
        const float* b2_l   = b2   + (size_t)l * Dm;

        // qkv = h @ Wqkv^T + bqkv      [3200, 3072]
        split_kernel<<<(Mm * Dm + 255) / 256, 256>>>(h, ah, al, Mm * Dm);
        split_kernel<<<(3 * Dm * Dm + 255) / 256, 256>>>(Wqkv_l, wh, wl, 3 * Dm * Dm);
        gemm_mma<false><<<dim3(Mm / BMt, 3 * Dm / BNt), NTHREADS, GEMM_SMEM_BYTES>>>(
            ah, al, ah, wh, wh, wl, 3, bqkv_l, qkv, 3 * Dm, Dm);

        // attention -> ctx             [3200, 1024]
        attn_kernel<<<Bm * Hm, 128>>>(qkv, ctx);

        // attn_out = ctx @ Wo^T + bo
        split_kernel<<<(Mm * Dm + 255) / 256, 256>>>(ctx, ah, al, Mm * Dm);
        split_kernel<<<(Dm * Dm + 255) / 256, 256>>>(Wo_l, wh, wl, Dm * Dm);
        gemm_mma<false><<<dim3(Mm / BMt, Dm / BNt), NTHREADS, GEMM_SMEM_BYTES>>>(
            ah, al, ah, wh, wh, wl, 3, bo_l, tmp, Dm, Dm);

        // h = LN(h + attn_out)
        ln_kernel<<<Mm, 256>>>(h, tmp, ln1w + (size_t)l * Dm, ln1b + (size_t)l * Dm);

        // ff = gelu(h @ W1^T + b1)     [3200, 4096]
        split_kernel<<<(Mm * Dm + 255) / 256, 256>>>(h, ah, al, Mm * Dm);
        split_kernel<<<(FFm * Dm + 255) / 256, 256>>>(W1_l, wh, wl, FFm * Dm);
        gemm_mma<true><<<dim3(Mm / BMt, FFm / BNt), NTHREADS, GEMM_SMEM_BYTES>>>(
            ah, al, ah, wh, wh, wl, 3, b1_l, ff, FFm, Dm);

        // ff2 = ff @ W2^T + b2         [3200, 1024], K = 4096
        split_kernel<<<(Mm * FFm + 255) / 256, 256>>>(ff, ah, al, Mm * FFm);
        split_kernel<<<(Dm * FFm + 255) / 256, 256>>>(W2_l, wh, wl, Dm * FFm);
        gemm_mma<false><<<dim3(Mm / BMt, Dm / BNt), NTHREADS, GEMM_SMEM_BYTES>>>(
            ah, al, ah, wh, wh, wl, 3, b2_l, tmp, Dm, FFm);

        // h = LN(h + ff2)
        ln_kernel<<<Mm, 256>>>(h, tmp, ln2w + (size_t)l * Dm, ln2b + (size_t)l * Dm);
    }

    // 3. ternary decoder
    absum_kernel<<<1024, 256>>>(decw);
    finalize_g_kernel<<<1, 256>>>();
    quant_kernel<<<(int)(((size_t)Vm * Dm + 255) / 256), 256>>>(decw);

    // out = h @ tw^T + dec_b           [3200, 32000]
    // 2 segments: Ah*tw + Al*tw (tw exact in fp16). grid.x = m-tiles so
    // consecutive blocks share the same tw panel (L2 reuse).
    split_kernel<<<(Mm * Dm + 255) / 256, 256>>>(h, ah, al, Mm * Dm);
    gemm_mma<false><<<dim3(Mm / BMt, Vm / BNt), NTHREADS, GEMM_SMEM_BYTES>>>(
        ah, al, (const __half*)0, twq, twq, (const __half*)0,
        2, decb, out, Vm, Dm);
}